// round 1
// baseline (speedup 1.0000x reference)
#include <cuda_runtime.h>

#define F_IN 3201

// ---------------------------------------------------------------------------
// Scratch: one big device global (no allocations allowed).
// Layout (float offsets):
#define OFF_HA   0ULL          // 8000*3201 = 25,608,000  (also holds bn0 out / layer2 out / layer4 out)
#define OFF_HB   25608000ULL   // 8000*1024
#define OFF_XL   33800000ULL   // 8000*1024
#define OFF_XR   41992000ULL   // 8000*1024
#define OFF_AGG  50184000ULL   // 8000*1024
#define OFF_E    58376000ULL   // 72000*2
#define OFF_EX   58520000ULL   // 72000*2
#define OFF_EMAX 58664000ULL   // 8000*2
#define OFF_DEN  58680000ULL   // 8000*2
#define OFF_DEG  58696000ULL   // 8000
#define OFF_SUM  58704000ULL   // 4096
#define OFF_SQ   58708096ULL   // 4096
#define OFF_MEAN 58712192ULL   // 4096
#define OFF_RSTD 58716288ULL   // 4096
#define OFF_PRED 58720384ULL   // 8000
// total 58,728,384 floats
__device__ float g_buf[58800000];

// ---------------------------------------------------------------------------
__device__ __forceinline__ void atomicMaxF(float* addr, float val) {
    if (val >= 0.f) atomicMax((int*)addr, __float_as_int(val));
    else            atomicMin((unsigned int*)addr, __float_as_uint(val));
}

__global__ void fill_k(float* __restrict__ p, long long n, float v) {
    long long i = (long long)blockIdx.x * blockDim.x + threadIdx.x;
    long long stride = (long long)gridDim.x * blockDim.x;
    for (; i < n; i += stride) p[i] = v;
}

// ---------------------------------------------------------------------------
// Column-wise sum / sumsq over rows (batchnorm stats, training mode)
__global__ void colstats_k(const float* __restrict__ H, int Nn, int F, int rows_per,
                           float* __restrict__ sum, float* __restrict__ sq) {
    int col = blockIdx.x * blockDim.x + threadIdx.x;
    if (col >= F) return;
    int r0 = blockIdx.y * rows_per;
    int r1 = min(r0 + rows_per, Nn);
    float s = 0.f, q = 0.f;
    for (int r = r0; r < r1; r++) {
        float v = H[(size_t)r * F + col];
        s += v; q += v * v;
    }
    atomicAdd(&sum[col], s);
    atomicAdd(&sq[col], q);
}

__global__ void finstats_k(const float* __restrict__ sum, const float* __restrict__ sq,
                           int Nn, int F, float* __restrict__ mean, float* __restrict__ rstd) {
    int c = blockIdx.x * blockDim.x + threadIdx.x;
    if (c >= F) return;
    float m = sum[c] / (float)Nn;
    float v = sq[c] / (float)Nn - m * m;
    v = v > 0.f ? v : 0.f;
    mean[c] = m;
    rstd[c] = rsqrtf(v + 1e-5f);
}

__global__ void bn_apply_k(const float* __restrict__ X, float* __restrict__ O,
                           long long total, int F,
                           const float* __restrict__ mean, const float* __restrict__ rstd,
                           const float* __restrict__ g, const float* __restrict__ b,
                           int relu) {
    long long i = (long long)blockIdx.x * blockDim.x + threadIdx.x;
    long long stride = (long long)gridDim.x * blockDim.x;
    for (; i < total; i += stride) {
        int c = (int)(i % F);
        float v = (X[i] - mean[c]) * rstd[c] * g[c] + b[c];
        if (relu) v = fmaxf(v, 0.f);
        O[i] = v;
    }
}

// ---------------------------------------------------------------------------
// fp32 tiled GEMM: C[M,N] = A[M,K] @ B[K,N], all row-major.
// BM=128, BN=64, BK=16, 256 threads, 8x4 per thread.
#define GBM 128
#define GBN 64
#define GBK 16
#define GTM 8
#define GTN 4
#define GPAD 4

__global__ __launch_bounds__(256) void sgemm_k(
    const float* __restrict__ A, const float* __restrict__ B, float* __restrict__ C,
    int M, int N, int K)
{
    __shared__ float As[GBK][GBM + GPAD];
    __shared__ float Bs[GBK][GBN];
    int tx = threadIdx.x & 15;   // 0..15 (cols)
    int ty = threadIdx.x >> 4;   // 0..15 (rows)
    int m0 = blockIdx.y * GBM;
    int n0 = blockIdx.x * GBN;

    float acc[GTM][GTN];
#pragma unroll
    for (int i = 0; i < GTM; i++)
#pragma unroll
        for (int j = 0; j < GTN; j++) acc[i][j] = 0.f;

    for (int k0 = 0; k0 < K; k0 += GBK) {
        // Load A tile: 128 x 16
#pragma unroll
        for (int t = 0; t < (GBM * GBK) / 256; t++) {
            int idx = threadIdx.x + t * 256;
            int i = idx >> 4;           // row within tile
            int j = idx & 15;           // k within tile
            int m = m0 + i, k = k0 + j;
            As[j][i] = (m < M && k < K) ? A[(size_t)m * K + k] : 0.f;
        }
        // Load B tile: 16 x 64  (N assumed multiple of 64)
#pragma unroll
        for (int t = 0; t < (GBK * GBN) / 256; t++) {
            int idx = threadIdx.x + t * 256;
            int r = idx >> 6;           // k within tile
            int c = idx & 63;
            int k = k0 + r;
            Bs[r][c] = (k < K) ? B[(size_t)k * N + (n0 + c)] : 0.f;
        }
        __syncthreads();
#pragma unroll
        for (int k = 0; k < GBK; k++) {
            float ra[GTM], rb[GTN];
#pragma unroll
            for (int i = 0; i < GTM; i++) ra[i] = As[k][ty * GTM + i];
#pragma unroll
            for (int j = 0; j < GTN; j++) rb[j] = Bs[k][tx * GTN + j];
#pragma unroll
            for (int i = 0; i < GTM; i++)
#pragma unroll
                for (int j = 0; j < GTN; j++)
                    acc[i][j] += ra[i] * rb[j];
        }
        __syncthreads();
    }
#pragma unroll
    for (int i = 0; i < GTM; i++) {
        int m = m0 + ty * GTM + i;
        if (m < M) {
            float4 v = make_float4(acc[i][0], acc[i][1], acc[i][2], acc[i][3]);
            *(float4*)&C[(size_t)m * N + n0 + tx * GTN] = v;
        }
    }
}

// ---------------------------------------------------------------------------
// GATv2 edge kernels. Edge list = edge_index (2,E) + implicit self loops.
__device__ __forceinline__ void edge_endpoints(const int* __restrict__ ei, int E, int e,
                                               int& src, int& dst) {
    if (e < E) { src = ei[e]; dst = ei[E + e]; }
    else       { src = e - E; dst = e - E; }
}

// one warp per (edge, head): e[eh] = sum_c att[h,c]*lrelu(xl[src,h,c]+xr[dst,h,c])
__global__ void edge_score_k(const int* __restrict__ ei, int E, int Etot,
                             const float* __restrict__ xl, const float* __restrict__ xr,
                             const float* __restrict__ att, int Hh, int C,
                             float* __restrict__ ebuf, float* __restrict__ emax) {
    int warp = (blockIdx.x * blockDim.x + threadIdx.x) >> 5;
    int lane = threadIdx.x & 31;
    if (warp >= Etot * Hh) return;
    int e = warp / Hh, h = warp % Hh;
    int src, dst;
    edge_endpoints(ei, E, e, src, dst);
    const float* pl = xl + ((size_t)src * Hh + h) * C;
    const float* pr = xr + ((size_t)dst * Hh + h) * C;
    const float* pa = att + h * C;
    float acc = 0.f;
    for (int c = lane; c < C; c += 32) {
        float z = pl[c] + pr[c];
        z = z > 0.f ? z : 0.2f * z;
        acc += pa[c] * z;
    }
#pragma unroll
    for (int o = 16; o; o >>= 1) acc += __shfl_xor_sync(0xffffffffu, acc, o);
    if (lane == 0) {
        ebuf[(size_t)e * Hh + h] = acc;
        atomicMaxF(&emax[(size_t)dst * Hh + h], acc);
    }
}

// one thread per (edge, head): ex = exp(e - max); denom += ex; deg count
__global__ void edge_exp_k(const int* __restrict__ ei, int E, int Etot, int Hh,
                           const float* __restrict__ ebuf, const float* __restrict__ emax,
                           float* __restrict__ exbuf, float* __restrict__ denom,
                           float* __restrict__ deg) {
    int i = blockIdx.x * blockDim.x + threadIdx.x;
    if (i >= Etot * Hh) return;
    int e = i / Hh, h = i % Hh;
    int src, dst;
    edge_endpoints(ei, E, e, src, dst);
    float ex = __expf(ebuf[i] - emax[(size_t)dst * Hh + h]);
    exbuf[i] = ex;
    atomicAdd(&denom[(size_t)dst * Hh + h], ex);
    if (h == 0) atomicAdd(&deg[dst], 1.0f);
}

// one warp per (edge, head): agg[dst,h,:] += alpha * xl[src,h,:]
__global__ void edge_agg_k(const int* __restrict__ ei, int E, int Etot, int Hh, int C,
                           const float* __restrict__ xl, const float* __restrict__ exbuf,
                           const float* __restrict__ denom, float* __restrict__ agg) {
    int warp = (blockIdx.x * blockDim.x + threadIdx.x) >> 5;
    int lane = threadIdx.x & 31;
    if (warp >= Etot * Hh) return;
    int e = warp / Hh, h = warp % Hh;
    int src, dst;
    edge_endpoints(ei, E, e, src, dst);
    float alpha = exbuf[(size_t)e * Hh + h] / denom[(size_t)dst * Hh + h];
    const float* pl = xl + ((size_t)src * Hh + h) * C;
    float* pd = agg + ((size_t)dst * Hh + h) * C;
    for (int c = lane; c < C; c += 32)
        atomicAdd(&pd[c], alpha * pl[c]);
}

__global__ void gat_final_k(const float* __restrict__ agg, const float* __restrict__ deg,
                            const float* __restrict__ bias, float* __restrict__ out,
                            long long total, int HC, int relu) {
    long long i = (long long)blockIdx.x * blockDim.x + threadIdx.x;
    long long stride = (long long)gridDim.x * blockDim.x;
    for (; i < total; i += stride) {
        int n = (int)(i / HC);
        int j = (int)(i % HC);
        float v = agg[i] / deg[n] + bias[j];
        if (relu) v = fmaxf(v, 0.f);
        out[i] = v;
    }
}

// ---------------------------------------------------------------------------
// head: pred = sigmoid(h @ Wh + bh), one warp per node
__global__ void head_k(const float* __restrict__ h, const float* __restrict__ Wh,
                       const float* __restrict__ bh, float* __restrict__ pred,
                       int Nn, int C) {
    int warp = (blockIdx.x * blockDim.x + threadIdx.x) >> 5;
    int lane = threadIdx.x & 31;
    if (warp >= Nn) return;
    const float* p = h + (size_t)warp * C;
    float acc = 0.f;
    for (int c = lane; c < C; c += 32) acc += p[c] * Wh[c];
#pragma unroll
    for (int o = 16; o; o >>= 1) acc += __shfl_xor_sync(0xffffffffu, acc, o);
    if (lane == 0) {
        float x = acc + bh[0];
        pred[warp] = 1.f / (1.f + __expf(-x));
    }
}

__global__ void gather_k(const float* __restrict__ pred, const float* __restrict__ y,
                         const int* __restrict__ idx, float* __restrict__ out, int NT) {
    int i = blockIdx.x * blockDim.x + threadIdx.x;
    if (i >= NT) return;
    int n = idx[i];
    out[i] = pred[n];
    out[NT + i] = y[n];
}

// ---------------------------------------------------------------------------
extern "C" void kernel_launch(void* const* d_in, const int* in_sizes, int n_in,
                              void* d_out, int out_size) {
    const float* x      = (const float*)d_in[0];
    const int*   ei     = (const int*)d_in[1];
    const float* y      = (const float*)d_in[2];
    const int*   tidx   = (const int*)d_in[3];
    const float* bn0_g  = (const float*)d_in[4];
    const float* bn0_b  = (const float*)d_in[5];
    const float* W1l    = (const float*)d_in[6];
    const float* W1r    = (const float*)d_in[7];
    const float* a1     = (const float*)d_in[8];
    const float* b1     = (const float*)d_in[9];
    const float* bn1_g  = (const float*)d_in[10];
    const float* bn1_b  = (const float*)d_in[11];
    const float* W2l    = (const float*)d_in[12];
    const float* W2r    = (const float*)d_in[13];
    const float* a2     = (const float*)d_in[14];
    const float* b2     = (const float*)d_in[15];
    const float* bn2_g  = (const float*)d_in[16];
    const float* bn2_b  = (const float*)d_in[17];
    const float* W3l    = (const float*)d_in[18];
    const float* W3r    = (const float*)d_in[19];
    const float* a3     = (const float*)d_in[20];
    const float* b3     = (const float*)d_in[21];
    const float* bn3_g  = (const float*)d_in[22];
    const float* bn3_b  = (const float*)d_in[23];
    const float* W4l    = (const float*)d_in[24];
    const float* W4r    = (const float*)d_in[25];
    const float* a4     = (const float*)d_in[26];
    const float* b4     = (const float*)d_in[27];
    const float* Wh     = (const float*)d_in[28];
    const float* bh     = (const float*)d_in[29];

    const int Nn   = in_sizes[2];            // 8000
    const int E    = in_sizes[1] / 2;        // 64000
    const int Etot = E + Nn;                 // with self loops
    const int NT   = in_sizes[3];            // 4000

    float* buf = nullptr;
    cudaGetSymbolAddress((void**)&buf, g_buf);
    float* HA   = buf + OFF_HA;
    float* HB   = buf + OFF_HB;
    float* XL   = buf + OFF_XL;
    float* XR   = buf + OFF_XR;
    float* AGG  = buf + OFF_AGG;
    float* EB   = buf + OFF_E;
    float* EXB  = buf + OFF_EX;
    float* EMX  = buf + OFF_EMAX;
    float* DEN  = buf + OFF_DEN;
    float* DEG  = buf + OFF_DEG;
    float* SUM  = buf + OFF_SUM;
    float* SQ   = buf + OFF_SQ;
    float* MEAN = buf + OFF_MEAN;
    float* RSTD = buf + OFF_RSTD;
    float* PRED = buf + OFF_PRED;

    auto run_bn = [&](const float* in, float* out, int F, const float* g, const float* b,
                      int relu) {
        fill_k<<<16, 256>>>(SUM, F, 0.f);
        fill_k<<<16, 256>>>(SQ, F, 0.f);
        int rows_per = (Nn + 31) / 32;
        dim3 grid((F + 255) / 256, 32);
        colstats_k<<<grid, 256>>>(in, Nn, F, rows_per, SUM, SQ);
        finstats_k<<<(F + 255) / 256, 256>>>(SUM, SQ, Nn, F, MEAN, RSTD);
        long long total = (long long)Nn * F;
        bn_apply_k<<<2048, 256>>>(in, out, total, F, MEAN, RSTD, g, b, relu);
    };

    auto run_gat = [&](const float* hin, int Fin, const float* Wl, const float* Wr,
                       const float* att, const float* bias, int Hh, int C,
                       float* hout, int relu_out) {
        int HC = Hh * C;
        // node transforms
        dim3 gg(HC / GBN, (Nn + GBM - 1) / GBM);
        sgemm_k<<<gg, 256>>>(hin, Wl, XL, Nn, HC, Fin);
        sgemm_k<<<gg, 256>>>(hin, Wr, XR, Nn, HC, Fin);
        // reset accumulators
        fill_k<<<64, 256>>>(EMX, (long long)Nn * Hh, -3.0e38f);
        fill_k<<<64, 256>>>(DEN, (long long)Nn * Hh, 0.f);
        fill_k<<<64, 256>>>(DEG, (long long)Nn, 0.f);
        fill_k<<<4096, 256>>>(AGG, (long long)Nn * HC, 0.f);
        int EH = Etot * Hh;
        edge_score_k<<<(EH * 32 + 255) / 256, 256>>>(ei, E, Etot, XL, XR, att, Hh, C, EB, EMX);
        edge_exp_k<<<(EH + 255) / 256, 256>>>(ei, E, Etot, Hh, EB, EMX, EXB, DEN, DEG);
        edge_agg_k<<<(EH * 32 + 255) / 256, 256>>>(ei, E, Etot, Hh, C, XL, EXB, DEN, AGG);
        long long total = (long long)Nn * HC;
        gat_final_k<<<2048, 256>>>(AGG, DEG, bias, hout, total, HC, relu_out);
    };

    // bn0: x -> HA
    run_bn(x, HA, F_IN, bn0_g, bn0_b, 0);
    // layer 1: HA(3201) -> HB(1024), H=2 C=512
    run_gat(HA, F_IN, W1l, W1r, a1, b1, 2, 512, HB, 0);
    run_bn(HB, HB, 1024, bn1_g, bn1_b, 1);
    // layer 2: HB(1024) -> HA(512)
    run_gat(HB, 1024, W2l, W2r, a2, b2, 1, 512, HA, 0);
    run_bn(HA, HA, 512, bn2_g, bn2_b, 1);
    // layer 3: HA(512) -> HB(512)
    run_gat(HA, 512, W3l, W3r, a3, b3, 1, 512, HB, 0);
    run_bn(HB, HB, 512, bn3_g, bn3_b, 1);
    // layer 4: HB(512) -> HA(512), relu fused
    run_gat(HB, 512, W4l, W4r, a4, b4, 1, 512, HA, 1);
    // head + gather
    head_k<<<(Nn * 32 + 255) / 256, 256>>>(HA, Wh, bh, PRED, Nn, 512);
    gather_k<<<(NT + 255) / 256, 256>>>(PRED, y, tidx, (float*)d_out, NT);
}

// round 4
// speedup vs baseline: 2.0752x; 2.0752x over previous
#include <cuda_runtime.h>
#include <cstdint>

// ===========================================================================
#define LDA0 3232          // 3201 padded to /32

// float-offset layout in one big scratch
#define O_HA   0ULL            // 8000*3232
#define O_HB   25856000ULL     // 8000*1024
#define O_XL   34048000ULL     // 8000*1024
#define O_XR   42240000ULL     // 8000*1024
#define O_BT   50432000ULL     // 2048*3232
#define O_EB   57051136ULL     // 144000
#define O_ST   57195136ULL     // 4*3232
#define O_PRED 57208064ULL     // 8000
#define O_INT  57216064ULL     // int region
__device__ float g_buf[57500000];

// ===========================================================================
__device__ __forceinline__ uint32_t f2tf32(float x) {
    uint32_t r;
    asm("cvt.rna.tf32.f32 %0, %1;" : "=r"(r) : "f"(x));
    return r;
}

// ===========================================================================
// tf32 mma.sync GEMM: C[M, Ntot] = A[M,K] @ BT[Ntot,K]^T
// Output cols [0,HC) -> XL, [HC,2HC) -> XR. K % 32 == 0, Ntot % 128 == 0,
// HC % 128 == 0.
#define BM 128
#define BN 128
#define BK 32
#define SPAD 36

__global__ __launch_bounds__(256) void gemm_mma_k(
    const float* __restrict__ A, int lda,
    const float* __restrict__ BT, int ldb,
    float* __restrict__ XL, float* __restrict__ XR,
    int M, int K, int HC)
{
    __shared__ uint32_t As[BM][SPAD];
    __shared__ uint32_t Bs[BN][SPAD];
    int tid = threadIdx.x;
    int lane = tid & 31, wid = tid >> 5;
    int wm = wid & 3, wn = wid >> 2;        // warp grid 4(m) x 2(n)
    int g = lane >> 2, t = lane & 3;
    int m0 = blockIdx.y * BM, n0 = blockIdx.x * BN;

    float acc[2][8][4];
#pragma unroll
    for (int i = 0; i < 2; i++)
#pragma unroll
        for (int j = 0; j < 8; j++)
#pragma unroll
            for (int v = 0; v < 4; v++) acc[i][j][v] = 0.f;

    const int r_ld = tid >> 3;      // 0..31 base row for loads (row = r_ld + i*32)
    const int q_ld = tid & 7;       // k-chunk (4 floats)

    for (int k0 = 0; k0 < K; k0 += BK) {
        __syncthreads();
        // ---- A tile 128x32 (rows may tail past M)
#pragma unroll
        for (int i = 0; i < 4; i++) {
            int r = r_ld + i * 32;
            int m = m0 + r;
            float4 v = make_float4(0.f, 0.f, 0.f, 0.f);
            if (m < M) v = *(const float4*)(A + (size_t)m * lda + k0 + q_ld * 4);
            As[r][q_ld * 4 + 0] = f2tf32(v.x);
            As[r][q_ld * 4 + 1] = f2tf32(v.y);
            As[r][q_ld * 4 + 2] = f2tf32(v.z);
            As[r][q_ld * 4 + 3] = f2tf32(v.w);
        }
        // ---- B tile 128x32 (always full rows)
#pragma unroll
        for (int i = 0; i < 4; i++) {
            int r = r_ld + i * 32;
            float4 v = *(const float4*)(BT + (size_t)(n0 + r) * ldb + k0 + q_ld * 4);
            Bs[r][q_ld * 4 + 0] = f2tf32(v.x);
            Bs[r][q_ld * 4 + 1] = f2tf32(v.y);
            Bs[r][q_ld * 4 + 2] = f2tf32(v.z);
            Bs[r][q_ld * 4 + 3] = f2tf32(v.w);
        }
        __syncthreads();

#pragma unroll
        for (int ks = 0; ks < 4; ks++) {
            int kk = ks * 8;
            uint32_t a[2][4], b[8][2];
#pragma unroll
            for (int mt = 0; mt < 2; mt++) {
                int m = wm * 32 + mt * 16 + g;
                a[mt][0] = As[m][kk + t];
                a[mt][1] = As[m + 8][kk + t];
                a[mt][2] = As[m][kk + t + 4];
                a[mt][3] = As[m + 8][kk + t + 4];
            }
#pragma unroll
            for (int nt = 0; nt < 8; nt++) {
                int n = wn * 64 + nt * 8 + g;
                b[nt][0] = Bs[n][kk + t];
                b[nt][1] = Bs[n][kk + t + 4];
            }
#pragma unroll
            for (int mt = 0; mt < 2; mt++)
#pragma unroll
                for (int nt = 0; nt < 8; nt++) {
                    asm volatile(
                        "mma.sync.aligned.m16n8k8.row.col.f32.tf32.tf32.f32 "
                        "{%0,%1,%2,%3}, {%4,%5,%6,%7}, {%8,%9}, {%0,%1,%2,%3};"
                        : "+f"(acc[mt][nt][0]), "+f"(acc[mt][nt][1]),
                          "+f"(acc[mt][nt][2]), "+f"(acc[mt][nt][3])
                        : "r"(a[mt][0]), "r"(a[mt][1]), "r"(a[mt][2]), "r"(a[mt][3]),
                          "r"(b[nt][0]), "r"(b[nt][1]));
                }
        }
    }

    // ---- epilogue: whole block is in one of XL/XR (HC % 128 == 0)
    float* Cout;
    int cbase;
    if (n0 < HC) { Cout = XL; cbase = n0; }
    else         { Cout = XR; cbase = n0 - HC; }
#pragma unroll
    for (int mt = 0; mt < 2; mt++) {
        int m = m0 + wm * 32 + mt * 16 + g;
#pragma unroll
        for (int nt = 0; nt < 8; nt++) {
            int c = cbase + wn * 64 + nt * 8 + 2 * t;
            if (m < M)
                *(float2*)(Cout + (size_t)m * HC + c) = make_float2(acc[mt][nt][0], acc[mt][nt][1]);
            if (m + 8 < M)
                *(float2*)(Cout + (size_t)(m + 8) * HC + c) = make_float2(acc[mt][nt][2], acc[mt][nt][3]);
        }
    }
}

// ===========================================================================
__global__ void transpose_k(const float* __restrict__ W, float* __restrict__ WT,
                            int K, int Nc, int ldbt) {
    __shared__ float t[32][33];
    int n0 = blockIdx.x * 32, k0 = blockIdx.y * 32;
#pragma unroll
    for (int i = 0; i < 32; i += 8) {
        int k = k0 + threadIdx.y + i, n = n0 + threadIdx.x;
        if (k < K && n < Nc) t[threadIdx.y + i][threadIdx.x] = W[(size_t)k * Nc + n];
    }
    __syncthreads();
#pragma unroll
    for (int i = 0; i < 32; i += 8) {
        int n = n0 + threadIdx.y + i, k = k0 + threadIdx.x;
        if (k < K && n < Nc) WT[(size_t)n * ldbt + k] = t[threadIdx.x][threadIdx.y + i];
    }
}

__global__ void fill_k(float* __restrict__ p, long long n, float v) {
    long long i = (long long)blockIdx.x * blockDim.x + threadIdx.x;
    long long st = (long long)gridDim.x * blockDim.x;
    for (; i < n; i += st) p[i] = v;
}
__global__ void fillint_k(int* __restrict__ p, int n, int v) {
    int i = blockIdx.x * blockDim.x + threadIdx.x;
    if (i < n) p[i] = v;
}
__global__ void padzero_k(float* __restrict__ H, int Nn, int F, int ld) {
    int i = blockIdx.x * blockDim.x + threadIdx.x;
    int pad = ld - F;
    if (i >= Nn * pad) return;
    int r = i / pad, c = F + i % pad;
    H[(size_t)r * ld + c] = 0.f;
}

// ===========================================================================
// CSR build (edges + self loops, grouped by dst)
__device__ __forceinline__ void edge_ep(const int* __restrict__ ei, int E, int e, int& s, int& d) {
    if (e < E) { s = ei[e]; d = ei[E + e]; }
    else       { s = e - E; d = e - E; }
}
__global__ void hist_k(const int* __restrict__ ei, int E, int Etot, int* __restrict__ cnt) {
    int i = blockIdx.x * blockDim.x + threadIdx.x;
    if (i >= Etot) return;
    int s, d; edge_ep(ei, E, i, s, d);
    atomicAdd(&cnt[d], 1);
}
__global__ void scan8000_k(const int* __restrict__ cnt, int* __restrict__ rowptr, int n) {
    __shared__ int sh[1024];
    int tid = threadIdx.x;
    int vals[8]; int s = 0;
#pragma unroll
    for (int j = 0; j < 8; j++) {
        int i = tid * 8 + j;
        vals[j] = (i < n) ? cnt[i] : 0;
        s += vals[j];
    }
    sh[tid] = s; __syncthreads();
    for (int off = 1; off < 1024; off <<= 1) {
        int v = (tid >= off) ? sh[tid - off] : 0;
        __syncthreads();
        sh[tid] += v;
        __syncthreads();
    }
    int run = sh[tid] - s;
#pragma unroll
    for (int j = 0; j < 8; j++) {
        int i = tid * 8 + j;
        if (i < n) rowptr[i] = run;
        run += vals[j];
    }
    if (tid == 1023) rowptr[n] = run;
}
__global__ void scatter_k(const int* __restrict__ ei, int E, int Etot,
                          const int* __restrict__ rowptr, int* __restrict__ fil,
                          int* __restrict__ csr_src) {
    int i = blockIdx.x * blockDim.x + threadIdx.x;
    if (i >= Etot) return;
    int s, d; edge_ep(ei, E, i, s, d);
    int pos = rowptr[d] + atomicAdd(&fil[d], 1);
    csr_src[pos] = s;
}

// ===========================================================================
// BatchNorm (training-mode stats)
__global__ void colstats_k(const float* __restrict__ H, int ldi, int Nn, int F, int rows_per,
                           float* __restrict__ sum, float* __restrict__ sq) {
    int col = blockIdx.x * blockDim.x + threadIdx.x;
    if (col >= F) return;
    int r0 = blockIdx.y * rows_per;
    int r1 = min(r0 + rows_per, Nn);
    float s = 0.f, q = 0.f;
    for (int r = r0; r < r1; r++) {
        float v = H[(size_t)r * ldi + col];
        s += v; q += v * v;
    }
    atomicAdd(&sum[col], s);
    atomicAdd(&sq[col], q);
}
__global__ void finstats_k(const float* __restrict__ sum, const float* __restrict__ sq,
                           int Nn, int F, float* __restrict__ mean, float* __restrict__ rstd) {
    int c = blockIdx.x * blockDim.x + threadIdx.x;
    if (c >= F) return;
    float m = sum[c] / (float)Nn;
    float v = sq[c] / (float)Nn - m * m;
    v = v > 0.f ? v : 0.f;
    mean[c] = m;
    rstd[c] = rsqrtf(v + 1e-5f);
}
__global__ void bn_apply_k(const float* __restrict__ X, int ldi, float* __restrict__ O, int ldo,
                           long long total, int F,
                           const float* __restrict__ mean, const float* __restrict__ rstd,
                           const float* __restrict__ g, const float* __restrict__ b, int relu) {
    long long i = (long long)blockIdx.x * blockDim.x + threadIdx.x;
    long long st = (long long)gridDim.x * blockDim.x;
    for (; i < total; i += st) {
        int r = (int)(i / F), c = (int)(i % F);
        float v = (X[(size_t)r * ldi + c] - mean[c]) * rstd[c] * g[c] + b[c];
        if (relu) v = fmaxf(v, 0.f);
        O[(size_t)r * ldo + c] = v;
    }
}

// ===========================================================================
// GATv2 edge scores (CSR order): EB[i*H+h]
__global__ void escore_k(const int* __restrict__ rowptr, const int* __restrict__ csr_src,
                         int Nn, int Etot,
                         const float* __restrict__ xl, const float* __restrict__ xr,
                         const float* __restrict__ att, int H, float* __restrict__ EB) {
    int warp = (blockIdx.x * blockDim.x + threadIdx.x) >> 5;
    int lane = threadIdx.x & 31;
    if (warp >= Etot * H) return;
    int i = warp / H, h = warp - i * H;
    // binary search dst for CSR entry i
    int lo = 0, hi = Nn;
    while (lo + 1 < hi) {
        int mid = (lo + hi) >> 1;
        if (rowptr[mid] <= i) lo = mid; else hi = mid;
    }
    int dst = lo;
    int src = csr_src[i];
    const float* pl = xl + ((size_t)src * H + h) * 512;
    const float* pr = xr + ((size_t)dst * H + h) * 512;
    const float* pa = att + h * 512;
    float acc = 0.f;
#pragma unroll
    for (int c = lane; c < 512; c += 32) {
        float z = pl[c] + pr[c];
        z = z > 0.f ? z : 0.2f * z;
        acc += pa[c] * z;
    }
#pragma unroll
    for (int o = 16; o; o >>= 1) acc += __shfl_xor_sync(0xffffffffu, acc, o);
    if (lane == 0) EB[(size_t)i * H + h] = acc;
}

// Fused softmax + weighted aggregation + mean + bias (+relu). Block per (node, head).
__global__ void node_k(const int* __restrict__ rowptr, const int* __restrict__ csr_src,
                       const float* __restrict__ xl, const float* __restrict__ EB,
                       const float* __restrict__ bias, float* __restrict__ out,
                       int H, int relu) {
    int n = blockIdx.x, h = blockIdx.y;
    int r0 = rowptr[n], r1 = rowptr[n + 1];
    int deg = r1 - r0;
    float mx = -3.4e38f;
    for (int i = r0; i < r1; i++) mx = fmaxf(mx, EB[(size_t)i * H + h]);
    int c = threadIdx.x;
    float denom = 0.f, a0 = 0.f, a1 = 0.f;
    for (int i = r0; i < r1; i++) {
        float ex = __expf(EB[(size_t)i * H + h] - mx);
        denom += ex;
        const float* p = xl + ((size_t)csr_src[i] * H + h) * 512;
        a0 += ex * p[c];
        a1 += ex * p[c + 256];
    }
    float inv = 1.f / (denom * (float)deg);
    float v0 = a0 * inv + bias[h * 512 + c];
    float v1 = a1 * inv + bias[h * 512 + c + 256];
    if (relu) { v0 = fmaxf(v0, 0.f); v1 = fmaxf(v1, 0.f); }
    float* po = out + ((size_t)n * H + h) * 512;
    po[c] = v0;
    po[c + 256] = v1;
}

// ===========================================================================
__global__ void head_k(const float* __restrict__ h, const float* __restrict__ Wh,
                       const float* __restrict__ bh, float* __restrict__ pred, int Nn) {
    int warp = (blockIdx.x * blockDim.x + threadIdx.x) >> 5;
    int lane = threadIdx.x & 31;
    if (warp >= Nn) return;
    const float* p = h + (size_t)warp * 512;
    float acc = 0.f;
#pragma unroll
    for (int c = lane; c < 512; c += 32) acc += p[c] * Wh[c];
#pragma unroll
    for (int o = 16; o; o >>= 1) acc += __shfl_xor_sync(0xffffffffu, acc, o);
    if (lane == 0) {
        float x = acc + bh[0];
        pred[warp] = 1.f / (1.f + __expf(-x));
    }
}
__global__ void gather_k(const float* __restrict__ pred, const float* __restrict__ y,
                         const int* __restrict__ idx, float* __restrict__ out, int NT) {
    int i = blockIdx.x * blockDim.x + threadIdx.x;
    if (i >= NT) return;
    int n = idx[i];
    out[i] = pred[n];
    out[NT + i] = y[n];
}

// ===========================================================================
extern "C" void kernel_launch(void* const* d_in, const int* in_sizes, int n_in,
                              void* d_out, int out_size) {
    const float* x     = (const float*)d_in[0];
    const int*   ei    = (const int*)d_in[1];
    const float* y     = (const float*)d_in[2];
    const int*   tidx  = (const int*)d_in[3];
    const float* bn0_g = (const float*)d_in[4];
    const float* bn0_b = (const float*)d_in[5];
    const float* W1l = (const float*)d_in[6],  *W1r = (const float*)d_in[7];
    const float* a1  = (const float*)d_in[8],  *b1  = (const float*)d_in[9];
    const float* bn1_g = (const float*)d_in[10], *bn1_b = (const float*)d_in[11];
    const float* W2l = (const float*)d_in[12], *W2r = (const float*)d_in[13];
    const float* a2  = (const float*)d_in[14], *b2  = (const float*)d_in[15];
    const float* bn2_g = (const float*)d_in[16], *bn2_b = (const float*)d_in[17];
    const float* W3l = (const float*)d_in[18], *W3r = (const float*)d_in[19];
    const float* a3  = (const float*)d_in[20], *b3  = (const float*)d_in[21];
    const float* bn3_g = (const float*)d_in[22], *bn3_b = (const float*)d_in[23];
    const float* W4l = (const float*)d_in[24], *W4r = (const float*)d_in[25];
    const float* a4  = (const float*)d_in[26], *b4  = (const float*)d_in[27];
    const float* Wh  = (const float*)d_in[28], *bh  = (const float*)d_in[29];

    const int Nn   = in_sizes[2];        // 8000
    const int FINv = in_sizes[0] / Nn;   // 3201
    const int E    = in_sizes[1] / 2;    // 64000
    const int Etot = E + Nn;
    const int NT   = in_sizes[3];

    float* buf = nullptr;
    cudaGetSymbolAddress((void**)&buf, g_buf);
    float* HA = buf + O_HA;
    float* HB = buf + O_HB;
    float* XL = buf + O_XL;
    float* XR = buf + O_XR;
    float* BT = buf + O_BT;
    float* EB = buf + O_EB;
    float* SUM  = buf + O_ST;
    float* SQ   = SUM + 3232;
    float* MEAN = SQ + 3232;
    float* RSTD = MEAN + 3232;
    float* PRED = buf + O_PRED;
    int* ib      = (int*)(buf + O_INT);
    int* CNT     = ib;
    int* ROWPTR  = ib + 8000;
    int* FIL     = ib + 16064;
    int* CSRSRC  = ib + 24064;

    // ---- CSR build (once per call)
    fillint_k<<<(Nn + 255) / 256, 256>>>(CNT, Nn, 0);
    fillint_k<<<(Nn + 255) / 256, 256>>>(FIL, Nn, 0);
    hist_k<<<(Etot + 255) / 256, 256>>>(ei, E, Etot, CNT);
    scan8000_k<<<1, 1024>>>(CNT, ROWPTR, Nn);
    scatter_k<<<(Etot + 255) / 256, 256>>>(ei, E, Etot, ROWPTR, FIL, CSRSRC);

    auto run_bn = [&](const float* in, int ldi, float* out, int ldo, int F,
                      const float* g, const float* b, int relu) {
        fill_k<<<16, 256>>>(SUM, F, 0.f);
        fill_k<<<16, 256>>>(SQ, F, 0.f);
        int rows_per = (Nn + 31) / 32;
        dim3 grid((F + 255) / 256, 32);
        colstats_k<<<grid, 256>>>(in, ldi, Nn, F, rows_per, SUM, SQ);
        finstats_k<<<(F + 255) / 256, 256>>>(SUM, SQ, Nn, F, MEAN, RSTD);
        bn_apply_k<<<2048, 256>>>(in, ldi, out, ldo, (long long)Nn * F, F, MEAN, RSTD, g, b, relu);
    };

    auto run_gat = [&](const float* hin, int lda, int K, const float* Wl, const float* Wr,
                       int Fw, const float* att, const float* bias, int H,
                       float* hout, int relu_out) {
        int HC = H * 512;
        int Ntot = 2 * HC;
        // Transpose weights into stacked BT [Ntot, K], ld = K (zero-pad tail cols)
        if (Fw != K) fill_k<<<2048, 256>>>(BT, (long long)Ntot * K, 0.f);
        dim3 tg((HC + 31) / 32, (Fw + 31) / 32);
        transpose_k<<<tg, dim3(32, 8)>>>(Wl, BT, Fw, HC, K);
        transpose_k<<<tg, dim3(32, 8)>>>(Wr, BT + (size_t)HC * K, Fw, HC, K);
        // GEMM: [Nn, K] @ [K, Ntot] -> XL | XR
        dim3 gg(Ntot / BN, (Nn + BM - 1) / BM);
        gemm_mma_k<<<gg, 256>>>(hin, lda, BT, K, XL, XR, Nn, K, HC);
        // Edge stages
        int EH = Etot * H;
        escore_k<<<(EH * 32 + 255) / 256, 256>>>(ROWPTR, CSRSRC, Nn, Etot, XL, XR, att, H, EB);
        node_k<<<dim3(Nn, H), 256>>>(ROWPTR, CSRSRC, XL, EB, bias, hout, H, relu_out);
    };

    // bn0: x(ld 3201) -> HA(ld 3232), pad zeros
    run_bn(x, FINv, HA, LDA0, FINv, bn0_g, bn0_b, 0);
    padzero_k<<<(Nn * (LDA0 - FINv) + 255) / 256, 256>>>(HA, Nn, FINv, LDA0);
    // layer 1: HA -> HB [8000,1024], H=2
    run_gat(HA, LDA0, LDA0, W1l, W1r, FINv, a1, b1, 2, HB, 0);
    run_bn(HB, 1024, HB, 1024, 1024, bn1_g, bn1_b, 1);
    // layer 2: HB(K=1024) -> HA [8000,512]
    run_gat(HB, 1024, 1024, W2l, W2r, 1024, a2, b2, 1, HA, 0);
    run_bn(HA, 512, HA, 512, 512, bn2_g, bn2_b, 1);
    // layer 3: HA -> HB
    run_gat(HA, 512, 512, W3l, W3r, 512, a3, b3, 1, HB, 0);
    run_bn(HB, 512, HB, 512, 512, bn3_g, bn3_b, 1);
    // layer 4: HB -> HA, relu fused
    run_gat(HB, 512, 512, W4l, W4r, 512, a4, b4, 1, HA, 1);
    // head + gather
    head_k<<<(Nn * 32 + 255) / 256, 256>>>(HA, Wh, bh, PRED, Nn);
    gather_k<<<(NT + 255) / 256, 256>>>(PRED, y, tidx, (float*)d_out, NT);
}

// round 6
// speedup vs baseline: 4.1469x; 1.9983x over previous
#include <cuda_runtime.h>
#include <cuda_bf16.h>
#include <cstdint>

// ===========================================================================
#define LDA0 3264            // 3201 padded to /64 (bf16 elems)

// float-offset layout (g_buf is zero-initialized at module load; "pad" regions
// are never written and therefore stay zero across all calls)
#define O_A1   0ULL            // bf16 [8000*3264]   = 13,056,000 floats
#define O_A2   13056000ULL     // bf16 [8000*1024]   (also A3/A4 with ld 512)
#define O_XL   17152000ULL     // f32 8000*1024
#define O_XR   25344000ULL     // f32 8000*1024
#define O_H1   33536000ULL     // f32 8000*1024
#define O_H2   41728000ULL     // f32 8000*512
#define O_H3   45824000ULL     // f32 8000*512
#define O_H4   49920000ULL     // f32 8000*512
#define O_BT1  54016000ULL     // bf16 2048*3264 = 3,342,336 floats
#define O_BT2  57358336ULL     // bf16 1024*1024 = 524,288 floats
#define O_BT3  57882624ULL     // bf16 1024*512  = 262,144 floats
#define O_BT4  58144768ULL     // bf16 1024*512
#define O_STAT 58406912ULL     // SUM/SQ/MEAN/RSTD 4*3264
#define O_PRED 58419968ULL     // 8000
#define O_INT  58427968ULL     // ints: CNT[8064], ROWPTR[8064], CSRSRC[72000]
__device__ float g_buf[58600000];

// ===========================================================================
// bf16 mma.sync GEMM: C[M, Ntot] = A[M,K] @ BT[Ntot,K]^T, fp32 accumulate.
// Output cols [0,HC) -> XL, [HC,2HC) -> XR. K%32==0, Ntot%128==0, HC%128==0.
#define BM 128
#define BN 128
#define BK 32
#define PADW 20        // u32 (bf16-pair) columns per smem row: 16 data + 4 pad

__global__ __launch_bounds__(256) void gemm_bf16_k(
    const __nv_bfloat16* __restrict__ A, int lda,
    const __nv_bfloat16* __restrict__ BT, int ldb,
    float* __restrict__ XL, float* __restrict__ XR,
    int M, int K, int HC)
{
    __shared__ uint32_t As[BM][PADW];
    __shared__ uint32_t Bs[BN][PADW];
    int tid = threadIdx.x;
    int lane = tid & 31, wid = tid >> 5;
    int wm = wid & 3, wn = wid >> 2;      // warp grid 4(m) x 2(n), warp tile 32x64
    int g = lane >> 2, t = lane & 3;
    int m0 = blockIdx.y * BM, n0 = blockIdx.x * BN;

    float acc[2][8][4];
#pragma unroll
    for (int i = 0; i < 2; i++)
#pragma unroll
        for (int j = 0; j < 8; j++)
#pragma unroll
            for (int v = 0; v < 4; v++) acc[i][j][v] = 0.f;

    const int r4 = tid >> 2;     // 0..63 (row), 2 passes of 64 rows
    const int q4 = tid & 3;      // which uint4 (8 bf16) within the 32-k row

    for (int k0 = 0; k0 < K; k0 += BK) {
        __syncthreads();
        // A tile 128x32 bf16 (rows may tail past M)
#pragma unroll
        for (int i = 0; i < 2; i++) {
            int r = r4 + i * 64;
            int m = m0 + r;
            uint4 v = make_uint4(0u, 0u, 0u, 0u);
            if (m < M) v = *(const uint4*)(A + (size_t)m * lda + k0 + q4 * 8);
            As[r][q4 * 4 + 0] = v.x; As[r][q4 * 4 + 1] = v.y;
            As[r][q4 * 4 + 2] = v.z; As[r][q4 * 4 + 3] = v.w;
        }
        // B tile 128x32 bf16 (always full)
#pragma unroll
        for (int i = 0; i < 2; i++) {
            int r = r4 + i * 64;
            uint4 v = *(const uint4*)(BT + (size_t)(n0 + r) * ldb + k0 + q4 * 8);
            Bs[r][q4 * 4 + 0] = v.x; Bs[r][q4 * 4 + 1] = v.y;
            Bs[r][q4 * 4 + 2] = v.z; Bs[r][q4 * 4 + 3] = v.w;
        }
        __syncthreads();

#pragma unroll
        for (int ks = 0; ks < 2; ks++) {
            int kkp = ks * 8;     // pair offset (16 k per step)
            uint32_t a[2][4], b[8][2];
#pragma unroll
            for (int mt = 0; mt < 2; mt++) {
                int m = wm * 32 + mt * 16 + g;
                a[mt][0] = As[m][kkp + t];
                a[mt][1] = As[m + 8][kkp + t];
                a[mt][2] = As[m][kkp + t + 4];
                a[mt][3] = As[m + 8][kkp + t + 4];
            }
#pragma unroll
            for (int nt = 0; nt < 8; nt++) {
                int n = wn * 64 + nt * 8 + g;
                b[nt][0] = Bs[n][kkp + t];
                b[nt][1] = Bs[n][kkp + t + 4];
            }
#pragma unroll
            for (int mt = 0; mt < 2; mt++)
#pragma unroll
                for (int nt = 0; nt < 8; nt++) {
                    asm volatile(
                        "mma.sync.aligned.m16n8k16.row.col.f32.bf16.bf16.f32 "
                        "{%0,%1,%2,%3}, {%4,%5,%6,%7}, {%8,%9}, {%0,%1,%2,%3};"
                        : "+f"(acc[mt][nt][0]), "+f"(acc[mt][nt][1]),
                          "+f"(acc[mt][nt][2]), "+f"(acc[mt][nt][3])
                        : "r"(a[mt][0]), "r"(a[mt][1]), "r"(a[mt][2]), "r"(a[mt][3]),
                          "r"(b[nt][0]), "r"(b[nt][1]));
                }
        }
    }

    // epilogue (HC % 128 == 0 -> whole block in one of XL/XR)
    float* Cout;
    int cbase;
    if (n0 < HC) { Cout = XL; cbase = n0; }
    else         { Cout = XR; cbase = n0 - HC; }
#pragma unroll
    for (int mt = 0; mt < 2; mt++) {
        int m = m0 + wm * 32 + mt * 16 + g;
#pragma unroll
        for (int nt = 0; nt < 8; nt++) {
            int c = cbase + wn * 64 + nt * 8 + 2 * t;
            if (m < M)
                *(float2*)(Cout + (size_t)m * HC + c) = make_float2(acc[mt][nt][0], acc[mt][nt][1]);
            if (m + 8 < M)
                *(float2*)(Cout + (size_t)(m + 8) * HC + c) = make_float2(acc[mt][nt][2], acc[mt][nt][3]);
        }
    }
}

// ===========================================================================
// Weight transpose (fp32 -> bf16): WT[n*ldbt + k] = bf16(W[k*Nc + n])
__global__ void transpose_bf_k(const float* __restrict__ W, __nv_bfloat16* __restrict__ WT,
                               int K, int Nc, int ldbt) {
    __shared__ float t[32][33];
    int n0 = blockIdx.x * 32, k0 = blockIdx.y * 32;
#pragma unroll
    for (int i = 0; i < 32; i += 8) {
        int k = k0 + threadIdx.y + i, n = n0 + threadIdx.x;
        if (k < K && n < Nc) t[threadIdx.y + i][threadIdx.x] = W[(size_t)k * Nc + n];
    }
    __syncthreads();
#pragma unroll
    for (int i = 0; i < 32; i += 8) {
        int n = n0 + threadIdx.y + i, k = k0 + threadIdx.x;
        if (k < K && n < Nc) WT[(size_t)n * ldbt + k] = __float2bfloat16(t[threadIdx.x][threadIdx.y + i]);
    }
}

// ===========================================================================
// CSR build (edges + self loops, grouped by dst). CNT must be zero at entry;
// scatter drains it back to zero (self-cleaning invariant).
__device__ __forceinline__ void edge_ep(const int* __restrict__ ei, int E, int e, int& s, int& d) {
    if (e < E) { s = ei[e]; d = ei[E + e]; }
    else       { s = e - E; d = e - E; }
}
__global__ void hist_k(const int* __restrict__ ei, int E, int Etot, int* __restrict__ cnt) {
    int i = blockIdx.x * blockDim.x + threadIdx.x;
    if (i >= Etot) return;
    int s, d; edge_ep(ei, E, i, s, d);
    atomicAdd(&cnt[d], 1);
}
__global__ void scan8000_k(const int* __restrict__ cnt, int* __restrict__ rowptr, int n) {
    __shared__ int sh[1024];
    int tid = threadIdx.x;
    int vals[8]; int s = 0;
#pragma unroll
    for (int j = 0; j < 8; j++) {
        int i = tid * 8 + j;
        vals[j] = (i < n) ? cnt[i] : 0;
        s += vals[j];
    }
    sh[tid] = s; __syncthreads();
    for (int off = 1; off < 1024; off <<= 1) {
        int v = (tid >= off) ? sh[tid - off] : 0;
        __syncthreads();
        sh[tid] += v;
        __syncthreads();
    }
    int run = sh[tid] - s;
#pragma unroll
    for (int j = 0; j < 8; j++) {
        int i = tid * 8 + j;
        if (i < n) rowptr[i] = run;
        run += vals[j];
    }
    if (tid == 1023) rowptr[n] = run;
}
__global__ void scatter_k(const int* __restrict__ ei, int E, int Etot,
                          const int* __restrict__ rowptr, int* __restrict__ cnt,
                          int* __restrict__ csr_src) {
    int i = blockIdx.x * blockDim.x + threadIdx.x;
    if (i >= Etot) return;
    int s, d; edge_ep(ei, E, i, s, d);
    int old = atomicAdd(&cnt[d], -1);        // drains cnt back to zero
    csr_src[rowptr[d] + old - 1] = s;
}

// ===========================================================================
// BatchNorm (training-mode stats). SUM/SQ zero at entry; finstats re-zeroes.
__global__ void colstats_k(const float* __restrict__ H, int ldi, int Nn, int F, int rows_per,
                           float* __restrict__ sum, float* __restrict__ sq) {
    int col = blockIdx.x * blockDim.x + threadIdx.x;
    if (col >= F) return;
    int r0 = blockIdx.y * rows_per;
    int r1 = min(r0 + rows_per, Nn);
    float s = 0.f, q = 0.f;
    for (int r = r0; r < r1; r++) {
        float v = H[(size_t)r * ldi + col];
        s += v; q += v * v;
    }
    atomicAdd(&sum[col], s);
    atomicAdd(&sq[col], q);
}
__global__ void finstats_k(float* __restrict__ sum, float* __restrict__ sq,
                           int Nn, int F, float* __restrict__ mean, float* __restrict__ rstd) {
    int c = blockIdx.x * blockDim.x + threadIdx.x;
    if (c >= F) return;
    float m = sum[c] / (float)Nn;
    float v = sq[c] / (float)Nn - m * m;
    v = v > 0.f ? v : 0.f;
    mean[c] = m;
    rstd[c] = rsqrtf(v + 1e-5f);
    sum[c] = 0.f;          // self-clean for next call
    sq[c] = 0.f;
}
// BN apply writing packed bf16 (GEMM A operand)
__global__ void bn_apply_bf_k(const float* __restrict__ X, int ldi,
                              __nv_bfloat16* __restrict__ O, int ldo,
                              long long total, int F,
                              const float* __restrict__ mean, const float* __restrict__ rstd,
                              const float* __restrict__ g, const float* __restrict__ b, int relu) {
    long long i = (long long)blockIdx.x * blockDim.x + threadIdx.x;
    long long st = (long long)gridDim.x * blockDim.x;
    for (; i < total; i += st) {
        int r = (int)(i / F), c = (int)(i % F);
        float v = (X[(size_t)r * ldi + c] - mean[c]) * rstd[c] * g[c] + b[c];
        if (relu) v = fmaxf(v, 0.f);
        O[(size_t)r * ldo + c] = __float2bfloat16(v);
    }
}

// ===========================================================================
// Fused GATv2 edge stage: per (node, head) block does online segment softmax
// + weighted aggregation + mean + bias (+relu). xl rows read once per edge.
__global__ __launch_bounds__(256) void node_fused_k(
    const int* __restrict__ rowptr, const int* __restrict__ csr_src,
    const float* __restrict__ xl, const float* __restrict__ xr,
    const float* __restrict__ att, const float* __restrict__ bias,
    float* __restrict__ out, int H, int relu)
{
    int n = blockIdx.x, h = blockIdx.y;
    __shared__ float xrs[512], atts[512], red[16];
    int c = threadIdx.x;
    int wid = c >> 5, lane = c & 31;
    size_t base = ((size_t)n * H + h) * 512;
    xrs[c] = xr[base + c];
    xrs[c + 256] = xr[base + c + 256];
    atts[c] = att[h * 512 + c];
    atts[c + 256] = att[h * 512 + c + 256];
    __syncthreads();

    int r0 = rowptr[n], r1 = rowptr[n + 1];
    float m = -3.4e38f, d = 0.f, acc0 = 0.f, acc1 = 0.f;
    for (int i = r0; i < r1; i++) {
        int src = csr_src[i];
        const float* p = xl + ((size_t)src * H + h) * 512;
        float l0 = p[c], l1 = p[c + 256];
        float z0 = l0 + xrs[c];        z0 = z0 > 0.f ? z0 : 0.2f * z0;
        float z1 = l1 + xrs[c + 256];  z1 = z1 > 0.f ? z1 : 0.2f * z1;
        float part = atts[c] * z0 + atts[c + 256] * z1;
#pragma unroll
        for (int o = 16; o; o >>= 1) part += __shfl_xor_sync(0xffffffffu, part, o);
        int par = (i - r0) & 1;        // parity double-buffer -> 1 sync per edge
        if (lane == 0) red[par * 8 + wid] = part;
        __syncthreads();
        float s = red[par * 8 + 0] + red[par * 8 + 1] + red[par * 8 + 2] + red[par * 8 + 3]
                + red[par * 8 + 4] + red[par * 8 + 5] + red[par * 8 + 6] + red[par * 8 + 7];
        float mn = fmaxf(m, s);
        float f = __expf(m - mn), e = __expf(s - mn);
        d = d * f + e;
        acc0 = acc0 * f + e * l0;
        acc1 = acc1 * f + e * l1;
        m = mn;
    }
    float inv = 1.f / (d * (float)(r1 - r0));
    float v0 = acc0 * inv + bias[h * 512 + c];
    float v1 = acc1 * inv + bias[h * 512 + c + 256];
    if (relu) { v0 = fmaxf(v0, 0.f); v1 = fmaxf(v1, 0.f); }
    out[base + c] = v0;
    out[base + c + 256] = v1;
}

// ===========================================================================
__global__ void head_k(const float* __restrict__ h, const float* __restrict__ Wh,
                       const float* __restrict__ bh, float* __restrict__ pred, int Nn) {
    int warp = (blockIdx.x * blockDim.x + threadIdx.x) >> 5;
    int lane = threadIdx.x & 31;
    if (warp >= Nn) return;
    const float* p = h + (size_t)warp * 512;
    float acc = 0.f;
#pragma unroll
    for (int c = lane; c < 512; c += 32) acc += p[c] * Wh[c];
#pragma unroll
    for (int o = 16; o; o >>= 1) acc += __shfl_xor_sync(0xffffffffu, acc, o);
    if (lane == 0) {
        float x = acc + bh[0];
        pred[warp] = 1.f / (1.f + __expf(-x));
    }
}
__global__ void gather_k(const float* __restrict__ pred, const float* __restrict__ y,
                         const int* __restrict__ idx, float* __restrict__ out, int NT) {
    int i = blockIdx.x * blockDim.x + threadIdx.x;
    if (i >= NT) return;
    int n = idx[i];
    out[i] = pred[n];
    out[NT + i] = y[n];
}

// ===========================================================================
extern "C" void kernel_launch(void* const* d_in, const int* in_sizes, int n_in,
                              void* d_out, int out_size) {
    const float* x     = (const float*)d_in[0];
    const int*   ei    = (const int*)d_in[1];
    const float* y     = (const float*)d_in[2];
    const int*   tidx  = (const int*)d_in[3];
    const float* bn0_g = (const float*)d_in[4];
    const float* bn0_b = (const float*)d_in[5];
    const float* W1l = (const float*)d_in[6],  *W1r = (const float*)d_in[7];
    const float* a1  = (const float*)d_in[8],  *b1  = (const float*)d_in[9];
    const float* bn1_g = (const float*)d_in[10], *bn1_b = (const float*)d_in[11];
    const float* W2l = (const float*)d_in[12], *W2r = (const float*)d_in[13];
    const float* a2  = (const float*)d_in[14], *b2  = (const float*)d_in[15];
    const float* bn2_g = (const float*)d_in[16], *bn2_b = (const float*)d_in[17];
    const float* W3l = (const float*)d_in[18], *W3r = (const float*)d_in[19];
    const float* a3  = (const float*)d_in[20], *b3  = (const float*)d_in[21];
    const float* bn3_g = (const float*)d_in[22], *bn3_b = (const float*)d_in[23];
    const float* W4l = (const float*)d_in[24], *W4r = (const float*)d_in[25];
    const float* a4  = (const float*)d_in[26], *b4  = (const float*)d_in[27];
    const float* Wh  = (const float*)d_in[28], *bh  = (const float*)d_in[29];

    const int Nn   = in_sizes[2];        // 8000
    const int FINv = in_sizes[0] / Nn;   // 3201
    const int E    = in_sizes[1] / 2;    // 64000
    const int Etot = E + Nn;
    const int NT   = in_sizes[3];

    float* buf = nullptr;
    cudaGetSymbolAddress((void**)&buf, g_buf);
    __nv_bfloat16* A1  = (__nv_bfloat16*)(buf + O_A1);
    __nv_bfloat16* A2  = (__nv_bfloat16*)(buf + O_A2);
    float* XL = buf + O_XL;
    float* XR = buf + O_XR;
    float* H1 = buf + O_H1;
    float* H2 = buf + O_H2;
    float* H3 = buf + O_H3;
    float* H4 = buf + O_H4;
    __nv_bfloat16* BT1 = (__nv_bfloat16*)(buf + O_BT1);
    __nv_bfloat16* BT2 = (__nv_bfloat16*)(buf + O_BT2);
    __nv_bfloat16* BT3 = (__nv_bfloat16*)(buf + O_BT3);
    __nv_bfloat16* BT4 = (__nv_bfloat16*)(buf + O_BT4);
    float* SUM  = buf + O_STAT;
    float* SQ   = SUM + 3264;
    float* MEAN = SQ + 3264;
    float* RSTD = MEAN + 3264;
    float* PRED = buf + O_PRED;
    int* CNT    = (int*)(buf + O_INT);
    int* ROWPTR = CNT + 8064;
    int* CSRSRC = ROWPTR + 8064;

    const int rows_per = (Nn + 31) / 32;
    const int GY = (Nn + BM - 1) / BM;

    auto run_bn_bf = [&](const float* in, int ldi, __nv_bfloat16* out, int ldo, int F,
                         const float* g, const float* b, int relu) {
        dim3 grid((F + 255) / 256, 32);
        colstats_k<<<grid, 256>>>(in, ldi, Nn, F, rows_per, SUM, SQ);
        finstats_k<<<(F + 255) / 256, 256>>>(SUM, SQ, Nn, F, MEAN, RSTD);
        bn_apply_bf_k<<<2048, 256>>>(in, ldi, out, ldo, (long long)Nn * F, F,
                                     MEAN, RSTD, g, b, relu);
    };

    // ---- BN0 -> A1 (bf16, padded ld 3264; pad cols statically zero)   [0-2]
    run_bn_bf(x, FINv, A1, LDA0, FINv, bn0_g, bn0_b, 0);
    // ---- weights layer 1 -> BT1 (pad cols statically zero)            [3-4]
    {
        dim3 tg(1024 / 32, (FINv + 31) / 32);
        transpose_bf_k<<<tg, dim3(32, 8)>>>(W1l, BT1, FINv, 1024, LDA0);
        transpose_bf_k<<<tg, dim3(32, 8)>>>(W1r, BT1 + (size_t)1024 * LDA0, FINv, 1024, LDA0);
    }
    // ---- GEMM layer 1   (launch index 5 -> profiled by ncu)           [5]
    gemm_bf16_k<<<dim3(2048 / BN, GY), 256>>>(A1, LDA0, BT1, LDA0, XL, XR, Nn, LDA0, 1024);
    // ---- CSR build (CNT zero-invariant; scatter drains it)            [6-8]
    hist_k<<<(Etot + 255) / 256, 256>>>(ei, E, Etot, CNT);
    scan8000_k<<<1, 1024>>>(CNT, ROWPTR, Nn);
    scatter_k<<<(Etot + 255) / 256, 256>>>(ei, E, Etot, ROWPTR, CNT, CSRSRC);
    // ---- GAT layer 1 edge stage -> H1                                 [9]
    node_fused_k<<<dim3(Nn, 2), 256>>>(ROWPTR, CSRSRC, XL, XR, a1, b1, H1, 2, 0);

    // ---- layer 2
    run_bn_bf(H1, 1024, A2, 1024, 1024, bn1_g, bn1_b, 1);
    {
        dim3 tg(512 / 32, 1024 / 32);
        transpose_bf_k<<<tg, dim3(32, 8)>>>(W2l, BT2, 1024, 512, 1024);
        transpose_bf_k<<<tg, dim3(32, 8)>>>(W2r, BT2 + (size_t)512 * 1024, 1024, 512, 1024);
    }
    gemm_bf16_k<<<dim3(1024 / BN, GY), 256>>>(A2, 1024, BT2, 1024, XL, XR, Nn, 1024, 512);
    node_fused_k<<<dim3(Nn, 1), 256>>>(ROWPTR, CSRSRC, XL, XR, a2, b2, H2, 1, 0);

    // ---- layer 3
    run_bn_bf(H2, 512, A2, 512, 512, bn2_g, bn2_b, 1);
    {
        dim3 tg(512 / 32, 512 / 32);
        transpose_bf_k<<<tg, dim3(32, 8)>>>(W3l, BT3, 512, 512, 512);
        transpose_bf_k<<<tg, dim3(32, 8)>>>(W3r, BT3 + (size_t)512 * 512, 512, 512, 512);
    }
    gemm_bf16_k<<<dim3(1024 / BN, GY), 256>>>(A2, 512, BT3, 512, XL, XR, Nn, 512, 512);
    node_fused_k<<<dim3(Nn, 1), 256>>>(ROWPTR, CSRSRC, XL, XR, a3, b3, H3, 1, 0);

    // ---- layer 4 (relu fused into edge stage)
    run_bn_bf(H3, 512, A2, 512, 512, bn3_g, bn3_b, 1);
    {
        dim3 tg(512 / 32, 512 / 32);
        transpose_bf_k<<<tg, dim3(32, 8)>>>(W4l, BT4, 512, 512, 512);
        transpose_bf_k<<<tg, dim3(32, 8)>>>(W4r, BT4 + (size_t)512 * 512, 512, 512, 512);
    }
    gemm_bf16_k<<<dim3(1024 / BN, GY), 256>>>(A2, 512, BT4, 512, XL, XR, Nn, 512, 512);
    node_fused_k<<<dim3(Nn, 1), 256>>>(ROWPTR, CSRSRC, XL, XR, a4, b4, H4, 1, 1);

    // ---- head + gather
    head_k<<<(Nn * 32 + 255) / 256, 256>>>(H4, Wh, bh, PRED, Nn);
    gather_k<<<(NT + 255) / 256, 256>>>(PRED, y, tidx, (float*)d_out, NT);
}

// round 7
// speedup vs baseline: 5.2366x; 1.2628x over previous
#include <cuda_runtime.h>
#include <cuda_bf16.h>
#include <cstdint>

// ===========================================================================
#define LDA0 3264            // 3201 padded to /64 (bf16 elems)

// float-offset layout (g_buf zero-initialized at load; pad regions never
// written -> statically zero across all calls)
#define O_A1   0ULL            // bf16 [8000*3264]
#define O_A2   13056000ULL     // bf16 [8000*1024] (also layers 3/4 with ld 512)
#define O_XL   17152000ULL     // f32 8000*1024
#define O_XR   25344000ULL     // f32 8000*1024
#define O_H1   33536000ULL     // f32 8000*1024
#define O_H2   41728000ULL     // f32 8000*512
#define O_H3   45824000ULL     // f32 8000*512
#define O_H4   49920000ULL     // f32 8000*512
#define O_BT1  54016000ULL     // bf16 2048*3264
#define O_BT2  57358336ULL     // bf16 1024*1024
#define O_BT3  57882624ULL     // bf16 1024*512
#define O_BT4  58144768ULL     // bf16 1024*512
#define O_STAT 58406912ULL     // SUM/SQ/MEAN/RSTD 4*3264
#define O_PRED 58419968ULL     // 8000
#define O_INT  58427968ULL     // ints: CNT[8064], ROWPTR[8064], CSRSRC[72000]
__device__ float g_buf[58600000];

// ===========================================================================
// bf16 mma.sync GEMM with cp.async double buffering + ldmatrix.
// C[M, Ntot] = A[M,K] @ BT[Ntot,K]^T, fp32 accum.
// Cols [0,HC) -> XL, [HC,2HC) -> XR. K%64==0, Ntot%128==0, HC%128==0.
#define BM 128
#define BN 128
#define BK 64
#define AST 72                       // bf16 row stride (64 data + 8 pad) = 144B
#define TILE_BH (BM * AST)           // bf16 elems per tile = 9216
#define TILE_B  (TILE_BH * 2)        // bytes per tile = 18432
#define SMEM_GEMM (4 * TILE_B)       // 2 stages x (A + B) = 73728 B

#define LDSM_X4(r0, r1, r2, r3, addr) \
    asm volatile("ldmatrix.sync.aligned.m8n8.x4.shared.b16 {%0,%1,%2,%3}, [%4];" \
        : "=r"(r0), "=r"(r1), "=r"(r2), "=r"(r3) : "r"(addr))

#define CP_ASYNC16(dst, src, sz) \
    asm volatile("cp.async.cg.shared.global [%0], [%1], 16, %2;" \
        :: "r"(dst), "l"(src), "r"(sz))

__global__ __launch_bounds__(256) void gemm_bf16_k(
    const __nv_bfloat16* __restrict__ A, int lda,
    const __nv_bfloat16* __restrict__ BT, int ldb,
    float* __restrict__ XL, float* __restrict__ XR,
    int M, int K, int HC)
{
    extern __shared__ __nv_bfloat16 smem[];
    const uint32_t smb = (uint32_t)__cvta_generic_to_shared(smem);
    int tid = threadIdx.x;
    int lane = tid & 31, wid = tid >> 5;
    int wm = wid & 3, wn = wid >> 2;      // warp grid 4(m) x 2(n), tile 32x64
    int m0 = blockIdx.y * BM, n0 = blockIdx.x * BN;

    // ldmatrix per-lane addressing
    int j = lane >> 3, sub = lane & 7;
    int mfrag = ((j & 1) << 3) + sub;     // A: m_block = j&1, k_block = j>>1
    int kfragA = (j >> 1) << 3;
    int nfrag = ((j >> 1) << 3) + sub;    // B: n_block = j>>1, k_block = j&1
    int kfragB = (j & 1) << 3;

    // cp.async per-thread addressing: 4 rows x 1 chunk each for A and B
    int row_ld = tid >> 3;                // 0..31
    int ch_ld = tid & 7;                  // 16B chunk 0..7 (8 bf16)

    float acc[2][8][4];
#pragma unroll
    for (int i = 0; i < 2; i++)
#pragma unroll
        for (int q = 0; q < 8; q++)
#pragma unroll
            for (int v = 0; v < 4; v++) acc[i][q][v] = 0.f;

    int ntiles = K / BK;

    auto load_stage = [&](int s, int k0) {
        uint32_t abase = smb + s * 2 * TILE_B;
        uint32_t bbase = abase + TILE_B;
#pragma unroll
        for (int i = 0; i < 4; i++) {
            int r = row_ld + i * 32;
            int m = m0 + r;
            const __nv_bfloat16* srcA =
                A + (size_t)(m < M ? m : 0) * lda + k0 + ch_ld * 8;
            uint32_t dstA = abase + (uint32_t)(r * AST + ch_ld * 8) * 2;
            CP_ASYNC16(dstA, srcA, (m < M) ? 16 : 0);
            const __nv_bfloat16* srcB = BT + (size_t)(n0 + r) * ldb + k0 + ch_ld * 8;
            uint32_t dstB = bbase + (uint32_t)(r * AST + ch_ld * 8) * 2;
            CP_ASYNC16(dstB, srcB, 16);
        }
        asm volatile("cp.async.commit_group;");
    };

    load_stage(0, 0);

    for (int t = 0; t < ntiles; t++) {
        if (t + 1 < ntiles) {
            load_stage((t + 1) & 1, (t + 1) * BK);
            asm volatile("cp.async.wait_group 1;");
        } else {
            asm volatile("cp.async.wait_group 0;");
        }
        __syncthreads();

        int s = t & 1;
        uint32_t abase = smb + s * 2 * TILE_B;
        uint32_t bbase = abase + TILE_B;
#pragma unroll
        for (int ks = 0; ks < 4; ks++) {
            uint32_t af[2][4];
#pragma unroll
            for (int mt = 0; mt < 2; mt++) {
                uint32_t addr = abase +
                    (uint32_t)((wm * 32 + mt * 16 + mfrag) * AST + ks * 16 + kfragA) * 2;
                LDSM_X4(af[mt][0], af[mt][1], af[mt][2], af[mt][3], addr);
            }
            uint32_t bf[8][2];
#pragma unroll
            for (int np = 0; np < 4; np++) {
                uint32_t r0, r1, r2, r3;
                uint32_t addr = bbase +
                    (uint32_t)((wn * 64 + np * 16 + nfrag) * AST + ks * 16 + kfragB) * 2;
                LDSM_X4(r0, r1, r2, r3, addr);
                bf[2 * np][0] = r0;     bf[2 * np][1] = r1;
                bf[2 * np + 1][0] = r2; bf[2 * np + 1][1] = r3;
            }
#pragma unroll
            for (int mt = 0; mt < 2; mt++)
#pragma unroll
                for (int nt = 0; nt < 8; nt++) {
                    asm volatile(
                        "mma.sync.aligned.m16n8k16.row.col.f32.bf16.bf16.f32 "
                        "{%0,%1,%2,%3}, {%4,%5,%6,%7}, {%8,%9}, {%0,%1,%2,%3};"
                        : "+f"(acc[mt][nt][0]), "+f"(acc[mt][nt][1]),
                          "+f"(acc[mt][nt][2]), "+f"(acc[mt][nt][3])
                        : "r"(af[mt][0]), "r"(af[mt][1]), "r"(af[mt][2]), "r"(af[mt][3]),
                          "r"(bf[nt][0]), "r"(bf[nt][1]));
                }
        }
        __syncthreads();
    }

    // epilogue (HC % 128 == 0 -> whole block in one of XL/XR)
    int g = lane >> 2, tq = lane & 3;
    float* Cout;
    int cbase;
    if (n0 < HC) { Cout = XL; cbase = n0; }
    else         { Cout = XR; cbase = n0 - HC; }
#pragma unroll
    for (int mt = 0; mt < 2; mt++) {
        int m = m0 + wm * 32 + mt * 16 + g;
#pragma unroll
        for (int nt = 0; nt < 8; nt++) {
            int c = cbase + wn * 64 + nt * 8 + 2 * tq;
            if (m < M)
                *(float2*)(Cout + (size_t)m * HC + c) = make_float2(acc[mt][nt][0], acc[mt][nt][1]);
            if (m + 8 < M)
                *(float2*)(Cout + (size_t)(m + 8) * HC + c) = make_float2(acc[mt][nt][2], acc[mt][nt][3]);
        }
    }
}

// ===========================================================================
// Weight transpose (fp32 -> bf16): WT[n*ldbt + k] = bf16(W[k*Nc + n])
__global__ void transpose_bf_k(const float* __restrict__ W, __nv_bfloat16* __restrict__ WT,
                               int K, int Nc, int ldbt) {
    __shared__ float t[32][33];
    int n0 = blockIdx.x * 32, k0 = blockIdx.y * 32;
#pragma unroll
    for (int i = 0; i < 32; i += 8) {
        int k = k0 + threadIdx.y + i, n = n0 + threadIdx.x;
        if (k < K && n < Nc) t[threadIdx.y + i][threadIdx.x] = W[(size_t)k * Nc + n];
    }
    __syncthreads();
#pragma unroll
    for (int i = 0; i < 32; i += 8) {
        int n = n0 + threadIdx.y + i, k = k0 + threadIdx.x;
        if (k < K && n < Nc) WT[(size_t)n * ldbt + k] = __float2bfloat16(t[threadIdx.x][threadIdx.y + i]);
    }
}

// ===========================================================================
// CSR build (edges + self loops, grouped by dst). CNT zero at entry;
// scatter drains it back to zero (self-cleaning, replay-safe).
__device__ __forceinline__ void edge_ep(const int* __restrict__ ei, int E, int e, int& s, int& d) {
    if (e < E) { s = ei[e]; d = ei[E + e]; }
    else       { s = e - E; d = e - E; }
}
__global__ void hist_k(const int* __restrict__ ei, int E, int Etot, int* __restrict__ cnt) {
    int i = blockIdx.x * blockDim.x + threadIdx.x;
    if (i >= Etot) return;
    int s, d; edge_ep(ei, E, i, s, d);
    atomicAdd(&cnt[d], 1);
}
__global__ void scan8000_k(const int* __restrict__ cnt, int* __restrict__ rowptr, int n) {
    __shared__ int sh[1024];
    int tid = threadIdx.x;
    int vals[8]; int s = 0;
#pragma unroll
    for (int q = 0; q < 8; q++) {
        int i = tid * 8 + q;
        vals[q] = (i < n) ? cnt[i] : 0;
        s += vals[q];
    }
    sh[tid] = s; __syncthreads();
    for (int off = 1; off < 1024; off <<= 1) {
        int v = (tid >= off) ? sh[tid - off] : 0;
        __syncthreads();
        sh[tid] += v;
        __syncthreads();
    }
    int run = sh[tid] - s;
#pragma unroll
    for (int q = 0; q < 8; q++) {
        int i = tid * 8 + q;
        if (i < n) rowptr[i] = run;
        run += vals[q];
    }
    if (tid == 1023) rowptr[n] = run;
}
__global__ void scatter_k(const int* __restrict__ ei, int E, int Etot,
                          const int* __restrict__ rowptr, int* __restrict__ cnt,
                          int* __restrict__ csr_src) {
    int i = blockIdx.x * blockDim.x + threadIdx.x;
    if (i >= Etot) return;
    int s, d; edge_ep(ei, E, i, s, d);
    int old = atomicAdd(&cnt[d], -1);        // drains cnt back to zero
    csr_src[rowptr[d] + old - 1] = s;
}

// ===========================================================================
// BatchNorm (training-mode stats). SUM/SQ zero at entry; finstats re-zeroes.
__global__ void colstats_k(const float* __restrict__ H, int ldi, int Nn, int F, int rows_per,
                           float* __restrict__ sum, float* __restrict__ sq) {
    int col = blockIdx.x * blockDim.x + threadIdx.x;
    if (col >= F) return;
    int r0 = blockIdx.y * rows_per;
    int r1 = min(r0 + rows_per, Nn);
    float s = 0.f, q = 0.f;
    for (int r = r0; r < r1; r++) {
        float v = H[(size_t)r * ldi + col];
        s += v; q += v * v;
    }
    atomicAdd(&sum[col], s);
    atomicAdd(&sq[col], q);
}
__global__ void finstats_k(float* __restrict__ sum, float* __restrict__ sq,
                           int Nn, int F, float* __restrict__ mean, float* __restrict__ rstd) {
    int c = blockIdx.x * blockDim.x + threadIdx.x;
    if (c >= F) return;
    float m = sum[c] / (float)Nn;
    float v = sq[c] / (float)Nn - m * m;
    v = v > 0.f ? v : 0.f;
    mean[c] = m;
    rstd[c] = rsqrtf(v + 1e-5f);
    sum[c] = 0.f;          // self-clean for next call / replay
    sq[c] = 0.f;
}
// BN apply writing packed bf16 (GEMM A operand)
__global__ void bn_apply_bf_k(const float* __restrict__ X, int ldi,
                              __nv_bfloat16* __restrict__ O, int ldo,
                              long long total, int F,
                              const float* __restrict__ mean, const float* __restrict__ rstd,
                              const float* __restrict__ g, const float* __restrict__ b, int relu) {
    long long i = (long long)blockIdx.x * blockDim.x + threadIdx.x;
    long long st = (long long)gridDim.x * blockDim.x;
    for (; i < total; i += st) {
        int r = (int)(i / F), c = (int)(i % F);
        float v = (X[(size_t)r * ldi + c] - mean[c]) * rstd[c] * g[c] + b[c];
        if (relu) v = fmaxf(v, 0.f);
        O[(size_t)r * ldo + c] = __float2bfloat16(v);
    }
}

// ===========================================================================
// Fused GATv2 edge stage: per (node, head) block does online segment softmax
// + weighted aggregation + mean + bias (+relu). xl rows read once per edge.
__global__ __launch_bounds__(256) void node_fused_k(
    const int* __restrict__ rowptr, const int* __restrict__ csr_src,
    const float* __restrict__ xl, const float* __restrict__ xr,
    const float* __restrict__ att, const float* __restrict__ bias,
    float* __restrict__ out, int H, int relu)
{
    int n = blockIdx.x, h = blockIdx.y;
    __shared__ float xrs[512], atts[512], red[16];
    int c = threadIdx.x;
    int wid = c >> 5, lane = c & 31;
    size_t base = ((size_t)n * H + h) * 512;
    xrs[c] = xr[base + c];
    xrs[c + 256] = xr[base + c + 256];
    atts[c] = att[h * 512 + c];
    atts[c + 256] = att[h * 512 + c + 256];
    __syncthreads();

    int r0 = rowptr[n], r1 = rowptr[n + 1];
    float m = -3.4e38f, d = 0.f, acc0 = 0.f, acc1 = 0.f;
    for (int i = r0; i < r1; i++) {
        int src = csr_src[i];
        const float* p = xl + ((size_t)src * H + h) * 512;
        float l0 = p[c], l1 = p[c + 256];
        float z0 = l0 + xrs[c];        z0 = z0 > 0.f ? z0 : 0.2f * z0;
        float z1 = l1 + xrs[c + 256];  z1 = z1 > 0.f ? z1 : 0.2f * z1;
        float part = atts[c] * z0 + atts[c + 256] * z1;
#pragma unroll
        for (int o = 16; o; o >>= 1) part += __shfl_xor_sync(0xffffffffu, part, o);
        int par = (i - r0) & 1;        // parity double-buffer -> 1 sync per edge
        if (lane == 0) red[par * 8 + wid] = part;
        __syncthreads();
        float s = red[par * 8 + 0] + red[par * 8 + 1] + red[par * 8 + 2] + red[par * 8 + 3]
                + red[par * 8 + 4] + red[par * 8 + 5] + red[par * 8 + 6] + red[par * 8 + 7];
        float mn = fmaxf(m, s);
        float f = __expf(m - mn), e = __expf(s - mn);
        d = d * f + e;
        acc0 = acc0 * f + e * l0;
        acc1 = acc1 * f + e * l1;
        m = mn;
    }
    float inv = 1.f / (d * (float)(r1 - r0));
    float v0 = acc0 * inv + bias[h * 512 + c];
    float v1 = acc1 * inv + bias[h * 512 + c + 256];
    if (relu) { v0 = fmaxf(v0, 0.f); v1 = fmaxf(v1, 0.f); }
    out[base + c] = v0;
    out[base + c + 256] = v1;
}

// ===========================================================================
__global__ void head_k(const float* __restrict__ h, const float* __restrict__ Wh,
                       const float* __restrict__ bh, float* __restrict__ pred, int Nn) {
    int warp = (blockIdx.x * blockDim.x + threadIdx.x) >> 5;
    int lane = threadIdx.x & 31;
    if (warp >= Nn) return;
    const float* p = h + (size_t)warp * 512;
    float acc = 0.f;
#pragma unroll
    for (int c = lane; c < 512; c += 32) acc += p[c] * Wh[c];
#pragma unroll
    for (int o = 16; o; o >>= 1) acc += __shfl_xor_sync(0xffffffffu, acc, o);
    if (lane == 0) {
        float x = acc + bh[0];
        pred[warp] = 1.f / (1.f + __expf(-x));
    }
}
__global__ void gather_k(const float* __restrict__ pred, const float* __restrict__ y,
                         const int* __restrict__ idx, float* __restrict__ out, int NT) {
    int i = blockIdx.x * blockDim.x + threadIdx.x;
    if (i >= NT) return;
    int n = idx[i];
    out[i] = pred[n];
    out[NT + i] = y[n];
}

// ===========================================================================
extern "C" void kernel_launch(void* const* d_in, const int* in_sizes, int n_in,
                              void* d_out, int out_size) {
    const float* x     = (const float*)d_in[0];
    const int*   ei    = (const int*)d_in[1];
    const float* y     = (const float*)d_in[2];
    const int*   tidx  = (const int*)d_in[3];
    const float* bn0_g = (const float*)d_in[4];
    const float* bn0_b = (const float*)d_in[5];
    const float* W1l = (const float*)d_in[6],  *W1r = (const float*)d_in[7];
    const float* a1  = (const float*)d_in[8],  *b1  = (const float*)d_in[9];
    const float* bn1_g = (const float*)d_in[10], *bn1_b = (const float*)d_in[11];
    const float* W2l = (const float*)d_in[12], *W2r = (const float*)d_in[13];
    const float* a2  = (const float*)d_in[14], *b2  = (const float*)d_in[15];
    const float* bn2_g = (const float*)d_in[16], *bn2_b = (const float*)d_in[17];
    const float* W3l = (const float*)d_in[18], *W3r = (const float*)d_in[19];
    const float* a3  = (const float*)d_in[20], *b3  = (const float*)d_in[21];
    const float* bn3_g = (const float*)d_in[22], *bn3_b = (const float*)d_in[23];
    const float* W4l = (const float*)d_in[24], *W4r = (const float*)d_in[25];
    const float* a4  = (const float*)d_in[26], *b4  = (const float*)d_in[27];
    const float* Wh  = (const float*)d_in[28], *bh  = (const float*)d_in[29];

    const int Nn   = in_sizes[2];        // 8000
    const int FINv = in_sizes[0] / Nn;   // 3201
    const int E    = in_sizes[1] / 2;    // 64000
    const int Etot = E + Nn;
    const int NT   = in_sizes[3];

    float* buf = nullptr;
    cudaGetSymbolAddress((void**)&buf, g_buf);
    __nv_bfloat16* A1  = (__nv_bfloat16*)(buf + O_A1);
    __nv_bfloat16* A2  = (__nv_bfloat16*)(buf + O_A2);
    float* XL = buf + O_XL;
    float* XR = buf + O_XR;
    float* H1 = buf + O_H1;
    float* H2 = buf + O_H2;
    float* H3 = buf + O_H3;
    float* H4 = buf + O_H4;
    __nv_bfloat16* BT1 = (__nv_bfloat16*)(buf + O_BT1);
    __nv_bfloat16* BT2 = (__nv_bfloat16*)(buf + O_BT2);
    __nv_bfloat16* BT3 = (__nv_bfloat16*)(buf + O_BT3);
    __nv_bfloat16* BT4 = (__nv_bfloat16*)(buf + O_BT4);
    float* SUM  = buf + O_STAT;
    float* SQ   = SUM + 3264;
    float* MEAN = SQ + 3264;
    float* RSTD = MEAN + 3264;
    float* PRED = buf + O_PRED;
    int* CNT    = (int*)(buf + O_INT);
    int* ROWPTR = CNT + 8064;
    int* CSRSRC = ROWPTR + 8064;

    const int rows_per = (Nn + 31) / 32;
    const int GY = (Nn + BM - 1) / BM;

    cudaFuncSetAttribute(gemm_bf16_k, cudaFuncAttributeMaxDynamicSharedMemorySize, SMEM_GEMM);

    auto run_bn_bf = [&](const float* in, int ldi, __nv_bfloat16* out, int ldo, int F,
                         const float* g, const float* b, int relu) {
        dim3 grid((F + 255) / 256, 32);
        colstats_k<<<grid, 256>>>(in, ldi, Nn, F, rows_per, SUM, SQ);
        finstats_k<<<(F + 255) / 256, 256>>>(SUM, SQ, Nn, F, MEAN, RSTD);
        bn_apply_bf_k<<<2048, 256>>>(in, ldi, out, ldo, (long long)Nn * F, F,
                                     MEAN, RSTD, g, b, relu);
    };

    // ---- BN0 -> A1 (bf16, ld 3264; pad cols statically zero)          [0-2]
    run_bn_bf(x, FINv, A1, LDA0, FINv, bn0_g, bn0_b, 0);
    // ---- weights layer 1 -> BT1 (pad cols statically zero)            [3-4]
    {
        dim3 tg(1024 / 32, (FINv + 31) / 32);
        transpose_bf_k<<<tg, dim3(32, 8)>>>(W1l, BT1, FINv, 1024, LDA0);
        transpose_bf_k<<<tg, dim3(32, 8)>>>(W1r, BT1 + (size_t)1024 * LDA0, FINv, 1024, LDA0);
    }
    // ---- GEMM layer 1 (launch index 5 -> profiled by ncu)             [5]
    gemm_bf16_k<<<dim3(2048 / BN, GY), 256, SMEM_GEMM>>>(A1, LDA0, BT1, LDA0, XL, XR, Nn, LDA0, 1024);
    // ---- CSR build                                                    [6-8]
    hist_k<<<(Etot + 255) / 256, 256>>>(ei, E, Etot, CNT);
    scan8000_k<<<1, 1024>>>(CNT, ROWPTR, Nn);
    scatter_k<<<(Etot + 255) / 256, 256>>>(ei, E, Etot, ROWPTR, CNT, CSRSRC);
    // ---- GAT layer 1 edge stage -> H1                                 [9]
    node_fused_k<<<dim3(Nn, 2), 256>>>(ROWPTR, CSRSRC, XL, XR, a1, b1, H1, 2, 0);

    // ---- layer 2
    run_bn_bf(H1, 1024, A2, 1024, 1024, bn1_g, bn1_b, 1);
    {
        dim3 tg(512 / 32, 1024 / 32);
        transpose_bf_k<<<tg, dim3(32, 8)>>>(W2l, BT2, 1024, 512, 1024);
        transpose_bf_k<<<tg, dim3(32, 8)>>>(W2r, BT2 + (size_t)512 * 1024, 1024, 512, 1024);
    }
    gemm_bf16_k<<<dim3(1024 / BN, GY), 256, SMEM_GEMM>>>(A2, 1024, BT2, 1024, XL, XR, Nn, 1024, 512);
    node_fused_k<<<dim3(Nn, 1), 256>>>(ROWPTR, CSRSRC, XL, XR, a2, b2, H2, 1, 0);

    // ---- layer 3
    run_bn_bf(H2, 512, A2, 512, 512, bn2_g, bn2_b, 1);
    {
        dim3 tg(512 / 32, 512 / 32);
        transpose_bf_k<<<tg, dim3(32, 8)>>>(W3l, BT3, 512, 512, 512);
        transpose_bf_k<<<tg, dim3(32, 8)>>>(W3r, BT3 + (size_t)512 * 512, 512, 512, 512);
    }
    gemm_bf16_k<<<dim3(1024 / BN, GY), 256, SMEM_GEMM>>>(A2, 512, BT3, 512, XL, XR, Nn, 512, 512);
    node_fused_k<<<dim3(Nn, 1), 256>>>(ROWPTR, CSRSRC, XL, XR, a3, b3, H3, 1, 0);

    // ---- layer 4 (relu fused into edge stage)
    run_bn_bf(H3, 512, A2, 512, 512, bn3_g, bn3_b, 1);
    {
        dim3 tg(512 / 32, 512 / 32);
        transpose_bf_k<<<tg, dim3(32, 8)>>>(W4l, BT4, 512, 512, 512);
        transpose_bf_k<<<tg, dim3(32, 8)>>>(W4r, BT4 + (size_t)512 * 512, 512, 512, 512);
    }
    gemm_bf16_k<<<dim3(1024 / BN, GY), 256, SMEM_GEMM>>>(A2, 512, BT4, 512, XL, XR, Nn, 512, 512);
    node_fused_k<<<dim3(Nn, 1), 256>>>(ROWPTR, CSRSRC, XL, XR, a4, b4, H4, 1, 1);

    // ---- head + gather
    head_k<<<(Nn * 32 + 255) / 256, 256>>>(H4, Wh, bh, PRED, Nn);
    gather_k<<<(NT + 255) / 256, 256>>>(PRED, y, tidx, (float*)d_out, NT);
}